// round 11
// baseline (speedup 1.0000x reference)
#include <cuda_runtime.h>
#include <cuda_fp16.h>
#include <cstdint>

#define NP     200
#define NPP    208
#define NCLS   10
#define NIMG   256
#define HWSZ   784
#define CIN    256
#define DD     64
#define MT     128
#define NTILES 1568         // 200704 / 128
#define TPB    256
#define FULL   0xffffffffu

// ---- smem byte offsets ----
#define S_X    0            // x tile [256 c][128 px] fp16, 256 B/row = 65536
#define S_W1   65536        // [64 o][256 c] fp16, 512 B/row          = 32768
#define S_H    98304        // [128 px][64] fp16, 128 B/row           = 16384
#define S_F    114688       // f [128][64] fp16                       = 16384
#define S_W2   131072       // [64][64] fp16                          = 8192
#define S_P    139264       // -2*prot [208][64] fp16                 = 26624
#define S_P2   165888       // [208] f32
#define S_B1   166784
#define S_B2   167040
#define S_S2   167296       // [128] f32
#define S_WA   167808       // [8][208] f32 = 6656
#define S_WB   174464
#define SMEM_TOTAL 181120

__device__ float g_part[NTILES * 2 * NPP];   // per-tile partial mins

__device__ __forceinline__ uint32_t smem_u32(const void* p) {
    uint32_t a;
    asm("{ .reg .u64 t; cvta.to.shared.u64 t, %1; cvt.u32.u64 %0, t; }" : "=r"(a) : "l"(p));
    return a;
}
__device__ __forceinline__ void ldm4(uint32_t* r, uint32_t addr) {
    asm volatile("ldmatrix.sync.aligned.m8n8.x4.shared.b16 {%0,%1,%2,%3}, [%4];"
        : "=r"(r[0]), "=r"(r[1]), "=r"(r[2]), "=r"(r[3]) : "r"(addr));
}
__device__ __forceinline__ void ldm4t(uint32_t* r, uint32_t addr) {
    asm volatile("ldmatrix.sync.aligned.m8n8.x4.trans.shared.b16 {%0,%1,%2,%3}, [%4];"
        : "=r"(r[0]), "=r"(r[1]), "=r"(r[2]), "=r"(r[3]) : "r"(addr));
}
__device__ __forceinline__ void mma16816(float* c, const uint32_t* a, const uint32_t* b) {
    asm volatile("mma.sync.aligned.m16n8k16.row.col.f32.f16.f16.f32 "
        "{%0,%1,%2,%3}, {%4,%5,%6,%7}, {%8,%9}, {%0,%1,%2,%3};"
        : "+f"(c[0]), "+f"(c[1]), "+f"(c[2]), "+f"(c[3])
        : "r"(a[0]), "r"(a[1]), "r"(a[2]), "r"(a[3]), "r"(b[0]), "r"(b[1]));
}
__device__ __forceinline__ uint32_t swz(int row, int cb, int rowb) {
    return (uint32_t)(row * rowb) + (uint32_t)(cb ^ ((row & 7) << 4));
}
__device__ __forceinline__ float sigmoidf_(float v) {
    return __fdividef(1.f, 1.f + __expf(-v));
}
__device__ __forceinline__ float wmin3(float m) {
    m = fminf(m, __shfl_xor_sync(FULL, m, 4));
    m = fminf(m, __shfl_xor_sync(FULL, m, 8));
    m = fminf(m, __shfl_xor_sync(FULL, m, 16));
    return m;
}

__global__ __launch_bounds__(TPB, 1)
void proto_mma(const float* __restrict__ x, const float* __restrict__ W1,
               const float* __restrict__ b1, const float* __restrict__ W2,
               const float* __restrict__ b2, const float* __restrict__ prot)
{
    extern __shared__ char sm8[];
    const uint32_t sb = smem_u32(sm8);
    float* sP2 = (float*)(sm8 + S_P2);
    float* sB1 = (float*)(sm8 + S_B1);
    float* sB2 = (float*)(sm8 + S_B2);
    float* sS2 = (float*)(sm8 + S_S2);
    float* sWA = (float*)(sm8 + S_WA);
    float* sWB = (float*)(sm8 + S_WB);

    const int tid  = threadIdx.x;
    const int w    = tid >> 5;
    const int lane = tid & 31;

    // ---- one-time weight staging (fp16, swizzled) ----
    for (int i = tid; i < DD * CIN; i += TPB) {
        int o = i >> 8, c = i & 255;
        *(__half*)(sm8 + S_W1 + swz(o, c * 2, 512)) = __float2half(W1[i]);
    }
    for (int i = tid; i < DD * DD; i += TPB) {
        int o = i >> 6, k = i & 63;
        *(__half*)(sm8 + S_W2 + swz(o, k * 2, 128)) = __float2half(W2[i]);
    }
    for (int i = tid; i < NPP * DD; i += TPB) {
        int p = i >> 6, c = i & 63;
        float v = (p < NP) ? (-2.0f * prot[p * DD + c]) : 0.0f;
        *(__half*)(sm8 + S_P + swz(p, c * 2, 128)) = __float2half(v);
    }
    if (tid < NPP) {
        float s = 0.f;
        if (tid < NP) {
            #pragma unroll
            for (int c = 0; c < DD; c++) { float v = prot[tid * DD + c]; s = fmaf(v, v, s); }
        }
        sP2[tid] = s;
    }
    if (tid < DD) { sB1[tid] = b1[tid]; sB2[tid] = b2[tid]; }
    __syncthreads();

    // ---- per-thread fragment geometry ----
    const int l7   = lane & 7;
    const int rowA = w * 16 + (lane & 15);
    const int c16  = lane & 16;
    const int swA  = (rowA & 7) << 4;
    const int rowB = (lane & 7) | ((lane & 16) >> 1);
    const int cB16 = (lane & 8) << 1;
    const int swB  = (rowB & 7) << 4;
    const int r1 = lane >> 2, e = (lane & 3) * 2;
    const int gr1 = w * 16 + r1, gr2 = gr1 + 8;
    const int swc = (r1 & 7) << 4;

    // trans-A base for X tile [c][px] (reads only warp's own 32B slice per row)
    const uint32_t aX  = sb + S_X + (uint32_t)((l7 + ((lane & 16) >> 1)) << 8)
                       + (uint32_t)(((w << 5) + ((lane & 8) << 1)) ^ (l7 << 4));
    const uint32_t aH  = sb + S_H + rowA * 128;
    const uint32_t aF  = sb + S_F + rowA * 128;
    const uint32_t bW1 = sb + S_W1 + rowB * 512;
    const uint32_t bW2 = sb + S_W2 + rowB * 128;
    const uint32_t bP  = sb + S_P  + rowB * 128;
    const float INF = __int_as_float(0x7f800000);

    // x staging geometry: warp owns its 16 px; lane handles quad (4 px) x 8 channels/iter
    const int quad  = lane & 3;
    const int cbase = lane >> 2;

    for (int tile = blockIdx.x; tile < NTILES; tile += gridDim.x) {
        const int px0  = tile * MT;
        const int nA   = px0 / HWSZ;
        const int bndg = (nA + 1) * HWSZ;
        const bool hasB = (px0 + MT - 1) >= bndg;
        const int bndw = bndg - px0;

        // ---- stage x -> [c][px] fp16 smem, WARP-PRIVATE px slice (no block sync) ----
        {
            const int gpx  = px0 + (w << 4) + (quad << 2);     // quads never straddle images
            const int n4   = gpx / HWSZ;
            const int pix4 = gpx - n4 * HWSZ;
            const float* bpx = x + ((size_t)n4 * CIN) * HWSZ + pix4;
            const uint32_t inrow = (uint32_t)((w << 5) + (quad << 3));
            #pragma unroll 8
            for (int i = 0; i < 32; i++) {
                const int c = (i << 3) + cbase;
                const float4 v = *(const float4*)(bpx + (size_t)c * HWSZ);
                __half2 p0 = __floats2half2_rn(v.x, v.y);
                __half2 p1 = __floats2half2_rn(v.z, v.w);
                uint32_t off = ((uint32_t)c << 8) + (inrow ^ ((uint32_t)(c & 7) << 4));
                uint2 st; st.x = *(uint32_t*)&p0; st.y = *(uint32_t*)&p1;
                *(uint2*)(sm8 + S_X + off) = st;
            }
            __syncwarp();
        }

        // ---- GEMM1: h = x . W1^T  (A fragments hoisted, 128 mma) ----
        float acc1[8][4];
        #pragma unroll
        for (int t = 0; t < 8; t++) { acc1[t][0]=0.f; acc1[t][1]=0.f; acc1[t][2]=0.f; acc1[t][3]=0.f; }
        {
            uint32_t a1r[16][4];
            #pragma unroll
            for (int kk = 0; kk < 16; kk++) ldm4t(a1r[kk], aX + kk * 4096);
            #pragma unroll
            for (int np = 0; np < 4; np++) {
                #pragma unroll
                for (int kk = 0; kk < 16; kk++) {
                    uint32_t b[4];
                    ldm4(b, bW1 + np * 8192 + (((kk * 32) | cB16) ^ swB));
                    mma16816(acc1[2*np],   a1r[kk], b);
                    mma16816(acc1[2*np+1], a1r[kk], b + 2);
                }
            }
        }
        // epi1: bias + relu -> h smem
        {
            const uint32_t h1 = sb + S_H + gr1 * 128, h2 = sb + S_H + gr2 * 128;
            #pragma unroll
            for (int t = 0; t < 8; t++) {
                int col = t * 8 + e;
                float2 bb = *(float2*)&sB1[col];
                float v0 = fmaxf(acc1[t][0] + bb.x, 0.f), v1 = fmaxf(acc1[t][1] + bb.y, 0.f);
                float v2 = fmaxf(acc1[t][2] + bb.x, 0.f), v3 = fmaxf(acc1[t][3] + bb.y, 0.f);
                __half2 p01 = __floats2half2_rn(v0, v1);
                __half2 p23 = __floats2half2_rn(v2, v3);
                uint32_t off = ((uint32_t)(col * 2)) ^ swc;
                *(uint32_t*)(sm8 + (h1 - sb) + off) = *(uint32_t*)&p01;
                *(uint32_t*)(sm8 + (h2 - sb) + off) = *(uint32_t*)&p23;
            }
            __syncwarp();
        }

        // ---- GEMM2: f_pre = h . W2^T  (32 mma) ----
        float acc2[8][4];
        #pragma unroll
        for (int t = 0; t < 8; t++) { acc2[t][0]=0.f; acc2[t][1]=0.f; acc2[t][2]=0.f; acc2[t][3]=0.f; }
        {
            uint32_t a2r[4][4];
            #pragma unroll
            for (int kk = 0; kk < 4; kk++) ldm4(a2r[kk], aH + (((kk * 32) | c16) ^ swA));
            #pragma unroll
            for (int kk = 0; kk < 4; kk++) {
                #pragma unroll
                for (int np = 0; np < 4; np++) {
                    uint32_t b[4];
                    ldm4(b, bW2 + np * 2048 + (((kk * 32) | cB16) ^ swB));
                    mma16816(acc2[2*np],   a2r[kk], b);
                    mma16816(acc2[2*np+1], a2r[kk], b + 2);
                }
            }
        }
        // epi2: sigmoid, fp32 sum f^2, fp16 f -> smem
        {
            const uint32_t f1 = sb + S_F + gr1 * 128, f2 = sb + S_F + gr2 * 128;
            float s2a = 0.f, s2b = 0.f;
            #pragma unroll
            for (int t = 0; t < 8; t++) {
                int col = t * 8 + e;
                float2 bb = *(float2*)&sB2[col];
                float v0 = sigmoidf_(acc2[t][0] + bb.x), v1 = sigmoidf_(acc2[t][1] + bb.y);
                float v2 = sigmoidf_(acc2[t][2] + bb.x), v3 = sigmoidf_(acc2[t][3] + bb.y);
                s2a = fmaf(v0, v0, s2a); s2a = fmaf(v1, v1, s2a);
                s2b = fmaf(v2, v2, s2b); s2b = fmaf(v3, v3, s2b);
                __half2 t01 = __floats2half2_rn(v0, v1);
                __half2 t23 = __floats2half2_rn(v2, v3);
                uint32_t off = ((uint32_t)(col * 2)) ^ swc;
                *(uint32_t*)(sm8 + (f1 - sb) + off) = *(uint32_t*)&t01;
                *(uint32_t*)(sm8 + (f2 - sb) + off) = *(uint32_t*)&t23;
            }
            s2a += __shfl_xor_sync(FULL, s2a, 1); s2a += __shfl_xor_sync(FULL, s2a, 2);
            s2b += __shfl_xor_sync(FULL, s2b, 1); s2b += __shfl_xor_sync(FULL, s2b, 2);
            if ((lane & 3) == 0) { sS2[gr1] = s2a; sS2[gr2] = s2b; }
            __syncwarp();
        }

        // ---- GEMM3: dot' = -2 f.p  (A hoisted, 104 mma) ----
        float acc3[26][4];
        #pragma unroll
        for (int t = 0; t < 26; t++) { acc3[t][0]=0.f; acc3[t][1]=0.f; acc3[t][2]=0.f; acc3[t][3]=0.f; }
        {
            uint32_t a3r[4][4];
            #pragma unroll
            for (int kk = 0; kk < 4; kk++) ldm4(a3r[kk], aF + (((kk * 32) | c16) ^ swA));
            #pragma unroll
            for (int kk = 0; kk < 4; kk++) {
                uint32_t kb = ((kk * 32) | cB16) ^ swB;
                #pragma unroll
                for (int np = 0; np < 13; np++) {
                    uint32_t b[4];
                    ldm4(b, bP + np * 2048 + kb);
                    mma16816(acc3[2*np],   a3r[kk], b);
                    mma16816(acc3[2*np+1], a3r[kk], b + 2);
                }
            }
        }

        // ---- epi3: distance + spatial min ----
        {
            const bool A1 = (w * 16 + r1)     < bndw;
            const bool A2 = (w * 16 + r1 + 8) < bndw;
            const float s2r1 = sS2[gr1], s2r2 = sS2[gr2];
            float* wA = sWA + w * NPP;
            float* wB = sWB + w * NPP;
            #pragma unroll
            for (int t = 0; t < 26; t++) {
                int col = t * 8 + e;
                float2 pp = *(float2*)&sP2[col];
                float d0 = fmaxf(acc3[t][0] + s2r1 + pp.x, 0.f);
                float d1 = fmaxf(acc3[t][1] + s2r1 + pp.y, 0.f);
                float d2 = fmaxf(acc3[t][2] + s2r2 + pp.x, 0.f);
                float d3 = fmaxf(acc3[t][3] + s2r2 + pp.y, 0.f);
                float a0 = fminf(A1 ? d0 : INF, A2 ? d2 : INF);
                float a1 = fminf(A1 ? d1 : INF, A2 ? d3 : INF);
                a0 = wmin3(a0); a1 = wmin3(a1);
                if (lane < 4) *(float2*)&wA[col] = make_float2(a0, a1);
                if (hasB) {
                    float b0 = fminf(A1 ? INF : d0, A2 ? INF : d2);
                    float b1v = fminf(A1 ? INF : d1, A2 ? INF : d3);
                    b0 = wmin3(b0); b1v = wmin3(b1v);
                    if (lane < 4) *(float2*)&wB[col] = make_float2(b0, b1v);
                }
            }
        }
        __syncthreads();
        if (tid < NPP) {
            float m = INF;
            #pragma unroll
            for (int ww = 0; ww < 8; ww++) m = fminf(m, sWA[ww * NPP + tid]);
            g_part[(size_t)(tile * 2) * NPP + tid] = m;
            float mb = INF;
            if (hasB) {
                #pragma unroll
                for (int ww = 0; ww < 8; ww++) mb = fminf(mb, sWB[ww * NPP + tid]);
            }
            g_part[(size_t)(tile * 2 + 1) * NPP + tid] = mb;
        }
        __syncthreads();
    }
}

// final: per-image min over tile partials + logits
__global__ void reduce_k(const float* __restrict__ lw, const float* __restrict__ lb,
                         float* __restrict__ logits, float* __restrict__ md)
{
    __shared__ float sm[NPP];
    const int n = blockIdx.x;
    const int tid = threadIdx.x;
    const float INF = __int_as_float(0x7f800000);

    if (tid < NPP) {
        int t0 = (n * HWSZ) >> 7;
        int t1 = (n * HWSZ + HWSZ - 1) >> 7;
        float m = INF;
        for (int t = t0; t <= t1; t++) {
            int nAt = (t * MT) / HWSZ;
            int slot = (nAt == n) ? 0 : 1;
            m = fminf(m, g_part[(size_t)(t * 2 + slot) * NPP + tid]);
        }
        sm[tid] = m;
        if (tid < NP) md[n * NP + tid] = m;
    }
    __syncthreads();

    const int w = tid >> 5, lane = tid & 31;
    for (int cls = w; cls < NCLS; cls += 8) {
        float s = 0.f;
        for (int p = lane; p < NP; p += 32)
            s = fmaf(-sm[p], lw[cls * NP + p], s);
        #pragma unroll
        for (int sh = 16; sh > 0; sh >>= 1)
            s += __shfl_xor_sync(FULL, s, sh);
        if (lane == 0) logits[n * NCLS + cls] = s + lb[cls];
    }
}

extern "C" void kernel_launch(void* const* d_in, const int* in_sizes, int n_in,
                              void* d_out, int out_size)
{
    const float* x    = (const float*)d_in[0];
    const float* W1   = (const float*)d_in[1];
    const float* b1   = (const float*)d_in[2];
    const float* W2   = (const float*)d_in[3];
    const float* b2   = (const float*)d_in[4];
    const float* prot = (const float*)d_in[5];
    const float* lw   = (const float*)d_in[6];
    const float* lb   = (const float*)d_in[7];

    float* out    = (float*)d_out;
    float* logits = out;                       // [256, 10]
    float* md     = out + NIMG * NCLS;         // [256, 200]

    cudaFuncSetAttribute(proto_mma, cudaFuncAttributeMaxDynamicSharedMemorySize, SMEM_TOTAL);
    int sms = 148;
    cudaDeviceGetAttribute(&sms, cudaDevAttrMultiProcessorCount, 0);

    proto_mma<<<sms, TPB, SMEM_TOTAL>>>(x, W1, b1, W2, b2, prot);
    reduce_k<<<NIMG, TPB>>>(lw, lb, logits, md);
}

// round 12
// speedup vs baseline: 1.0061x; 1.0061x over previous
#include <cuda_runtime.h>
#include <cuda_fp16.h>
#include <cstdint>

#define NP     200
#define NPP    208
#define NCLS   10
#define NIMG   256
#define HWSZ   784
#define CIN    256
#define DD     64
#define MT     128
#define NTILES 1568         // 200704 / 128
#define TPB    256
#define FULL   0xffffffffu

// ---- smem byte offsets ----
#define S_X    0            // x tile [256 c][128 px] fp16, 256 B/row = 65536
#define S_W1   65536        // [64 o][256 c] fp16, 512 B/row          = 32768
#define S_H    98304        // [128 px][64] fp16, 128 B/row           = 16384
#define S_F    114688       // f [128][64] fp16                       = 16384
#define S_W2   131072       // [64][64] fp16                          = 8192
#define S_P    139264       // -2*prot [208][64] fp16                 = 26624
#define S_P2   165888       // [208] f32
#define S_B1H  166784       // 32 x half2 = 128 B
#define S_B2   167040       // 64 f32
#define S_S2   167296       // [128] f32
#define S_WA   167808       // [8][208] f32 = 6656
#define S_WB   174464
#define SMEM_TOTAL 181120

__device__ float g_part[NTILES * 2 * NPP];   // per-tile partial mins

__device__ __forceinline__ uint32_t smem_u32(const void* p) {
    uint32_t a;
    asm("{ .reg .u64 t; cvta.to.shared.u64 t, %1; cvt.u32.u64 %0, t; }" : "=r"(a) : "l"(p));
    return a;
}
__device__ __forceinline__ void ldm4(uint32_t* r, uint32_t addr) {
    asm volatile("ldmatrix.sync.aligned.m8n8.x4.shared.b16 {%0,%1,%2,%3}, [%4];"
        : "=r"(r[0]), "=r"(r[1]), "=r"(r[2]), "=r"(r[3]) : "r"(addr));
}
__device__ __forceinline__ void ldm4t(uint32_t* r, uint32_t addr) {
    asm volatile("ldmatrix.sync.aligned.m8n8.x4.trans.shared.b16 {%0,%1,%2,%3}, [%4];"
        : "=r"(r[0]), "=r"(r[1]), "=r"(r[2]), "=r"(r[3]) : "r"(addr));
}
// fp32-accumulator mma (output-critical GEMM3)
__device__ __forceinline__ void mma16816(float* c, const uint32_t* a, const uint32_t* b) {
    asm volatile("mma.sync.aligned.m16n8k16.row.col.f32.f16.f16.f32 "
        "{%0,%1,%2,%3}, {%4,%5,%6,%7}, {%8,%9}, {%0,%1,%2,%3};"
        : "+f"(c[0]), "+f"(c[1]), "+f"(c[2]), "+f"(c[3])
        : "r"(a[0]), "r"(a[1]), "r"(a[2]), "r"(a[3]), "r"(b[0]), "r"(b[1]));
}
// fp16-accumulator mma (GEMM1/GEMM2, double-rate on legacy pipe)
__device__ __forceinline__ void mma16816h(uint32_t* c, const uint32_t* a, const uint32_t* b) {
    asm volatile("mma.sync.aligned.m16n8k16.row.col.f16.f16.f16.f16 "
        "{%0,%1}, {%2,%3,%4,%5}, {%6,%7}, {%0,%1};"
        : "+r"(c[0]), "+r"(c[1])
        : "r"(a[0]), "r"(a[1]), "r"(a[2]), "r"(a[3]), "r"(b[0]), "r"(b[1]));
}
__device__ __forceinline__ uint32_t swz(int row, int cb, int rowb) {
    return (uint32_t)(row * rowb) + (uint32_t)(cb ^ ((row & 7) << 4));
}
__device__ __forceinline__ float sigmoidf_(float v) {
    return __fdividef(1.f, 1.f + __expf(-v));
}
__device__ __forceinline__ float wmin3(float m) {
    m = fminf(m, __shfl_xor_sync(FULL, m, 4));
    m = fminf(m, __shfl_xor_sync(FULL, m, 8));
    m = fminf(m, __shfl_xor_sync(FULL, m, 16));
    return m;
}

__global__ __launch_bounds__(TPB, 1)
void proto_mma(const float* __restrict__ x, const float* __restrict__ W1,
               const float* __restrict__ b1, const float* __restrict__ W2,
               const float* __restrict__ b2, const float* __restrict__ prot)
{
    extern __shared__ char sm8[];
    const uint32_t sb = smem_u32(sm8);
    float*   sP2  = (float*)(sm8 + S_P2);
    __half2* sB1h = (__half2*)(sm8 + S_B1H);
    float*   sB2  = (float*)(sm8 + S_B2);
    float*   sS2  = (float*)(sm8 + S_S2);
    float*   sWA  = (float*)(sm8 + S_WA);
    float*   sWB  = (float*)(sm8 + S_WB);

    const int tid  = threadIdx.x;
    const int w    = tid >> 5;
    const int lane = tid & 31;

    // ---- one-time weight staging (fp16, swizzled) ----
    for (int i = tid; i < DD * CIN; i += TPB) {
        int o = i >> 8, c = i & 255;
        *(__half*)(sm8 + S_W1 + swz(o, c * 2, 512)) = __float2half(W1[i]);
    }
    for (int i = tid; i < DD * DD; i += TPB) {
        int o = i >> 6, k = i & 63;
        *(__half*)(sm8 + S_W2 + swz(o, k * 2, 128)) = __float2half(W2[i]);
    }
    for (int i = tid; i < NPP * DD; i += TPB) {
        int p = i >> 6, c = i & 63;
        float v = (p < NP) ? (-2.0f * prot[p * DD + c]) : 0.0f;
        *(__half*)(sm8 + S_P + swz(p, c * 2, 128)) = __float2half(v);
    }
    if (tid < NPP) {
        float s = 0.f;
        if (tid < NP) {
            #pragma unroll
            for (int c = 0; c < DD; c++) { float v = prot[tid * DD + c]; s = fmaf(v, v, s); }
        }
        sP2[tid] = s;
    }
    if (tid < 32) sB1h[tid] = __floats2half2_rn(b1[2 * tid], b1[2 * tid + 1]);
    if (tid < DD) sB2[tid] = b2[tid];
    __syncthreads();

    // ---- per-thread fragment geometry ----
    const int l7   = lane & 7;
    const int rowA = w * 16 + (lane & 15);
    const int c16  = lane & 16;
    const int swA  = (rowA & 7) << 4;
    const int rowB = (lane & 7) | ((lane & 16) >> 1);
    const int cB16 = (lane & 8) << 1;
    const int swB  = (rowB & 7) << 4;
    const int r1 = lane >> 2, e = (lane & 3) * 2;
    const int gr1 = w * 16 + r1, gr2 = gr1 + 8;
    const int swc = (r1 & 7) << 4;

    const uint32_t aX  = sb + S_X + (uint32_t)((l7 + ((lane & 16) >> 1)) << 8)
                       + (uint32_t)(((w << 5) + ((lane & 8) << 1)) ^ (l7 << 4));
    const uint32_t aH  = sb + S_H + rowA * 128;
    const uint32_t aF  = sb + S_F + rowA * 128;
    const uint32_t bW1 = sb + S_W1 + rowB * 512;
    const uint32_t bW2 = sb + S_W2 + rowB * 128;
    const uint32_t bP  = sb + S_P  + rowB * 128;
    const float INF = __int_as_float(0x7f800000);

    const int quad  = lane & 3;
    const int cbase = lane >> 2;

    for (int tile = blockIdx.x; tile < NTILES; tile += gridDim.x) {
        const int px0  = tile * MT;
        const int nA   = px0 / HWSZ;
        const int bndg = (nA + 1) * HWSZ;
        const bool hasB = (px0 + MT - 1) >= bndg;
        const int bndw = bndg - px0;

        // ---- stage x -> [c][px] fp16 smem, warp-private px slice ----
        {
            const int gpx  = px0 + (w << 4) + (quad << 2);     // quads never straddle images
            const int n4   = gpx / HWSZ;
            const int pix4 = gpx - n4 * HWSZ;
            const float* bpx = x + ((size_t)n4 * CIN) * HWSZ + pix4;
            const uint32_t inrow = (uint32_t)((w << 5) + (quad << 3));
            #pragma unroll 8
            for (int i = 0; i < 32; i++) {
                const int c = (i << 3) + cbase;
                const float4 v = *(const float4*)(bpx + (size_t)c * HWSZ);
                __half2 p0 = __floats2half2_rn(v.x, v.y);
                __half2 p1 = __floats2half2_rn(v.z, v.w);
                uint32_t off = ((uint32_t)c << 8) + (inrow ^ ((uint32_t)(c & 7) << 4));
                uint2 st; st.x = *(uint32_t*)&p0; st.y = *(uint32_t*)&p1;
                *(uint2*)(sm8 + S_X + off) = st;
            }
            __syncwarp();
        }

        // ---- GEMM1 (fp16 acc): h = x . W1^T ----
        uint32_t acc1h[8][2];
        #pragma unroll
        for (int t = 0; t < 8; t++) { acc1h[t][0] = 0u; acc1h[t][1] = 0u; }
        {
            uint32_t a1r[16][4];
            #pragma unroll
            for (int kk = 0; kk < 16; kk++) ldm4t(a1r[kk], aX + kk * 4096);
            #pragma unroll
            for (int np = 0; np < 4; np++) {
                #pragma unroll
                for (int kk = 0; kk < 16; kk++) {
                    uint32_t b[4];
                    ldm4(b, bW1 + np * 8192 + (((kk * 32) | cB16) ^ swB));
                    mma16816h(acc1h[2*np],   a1r[kk], b);
                    mma16816h(acc1h[2*np+1], a1r[kk], b + 2);
                }
            }
        }
        // epi1: bias + relu (half2) -> h smem
        {
            const uint32_t h1 = sb + S_H + gr1 * 128, h2 = sb + S_H + gr2 * 128;
            const __half2 z2 = __float2half2_rn(0.f);
            #pragma unroll
            for (int t = 0; t < 8; t++) {
                int col = t * 8 + e;
                __half2 bb = sB1h[col >> 1];
                __half2 a01 = *(__half2*)&acc1h[t][0];
                __half2 a23 = *(__half2*)&acc1h[t][1];
                __half2 v01 = __hmax2(__hadd2(a01, bb), z2);
                __half2 v23 = __hmax2(__hadd2(a23, bb), z2);
                uint32_t off = ((uint32_t)(col * 2)) ^ swc;
                *(uint32_t*)(sm8 + (h1 - sb) + off) = *(uint32_t*)&v01;
                *(uint32_t*)(sm8 + (h2 - sb) + off) = *(uint32_t*)&v23;
            }
            __syncwarp();
        }

        // ---- GEMM2 (fp16 acc): f_pre = h . W2^T ----
        uint32_t acc2h[8][2];
        #pragma unroll
        for (int t = 0; t < 8; t++) { acc2h[t][0] = 0u; acc2h[t][1] = 0u; }
        {
            uint32_t a2r[4][4];
            #pragma unroll
            for (int kk = 0; kk < 4; kk++) ldm4(a2r[kk], aH + (((kk * 32) | c16) ^ swA));
            #pragma unroll
            for (int kk = 0; kk < 4; kk++) {
                #pragma unroll
                for (int np = 0; np < 4; np++) {
                    uint32_t b[4];
                    ldm4(b, bW2 + np * 2048 + (((kk * 32) | cB16) ^ swB));
                    mma16816h(acc2h[2*np],   a2r[kk], b);
                    mma16816h(acc2h[2*np+1], a2r[kk], b + 2);
                }
            }
        }
        // epi2: sigmoid (fp32), fp32 sum f^2, fp16 f -> smem
        {
            const uint32_t f1 = sb + S_F + gr1 * 128, f2 = sb + S_F + gr2 * 128;
            float s2a = 0.f, s2b = 0.f;
            #pragma unroll
            for (int t = 0; t < 8; t++) {
                int col = t * 8 + e;
                float2 bb = *(float2*)&sB2[col];
                __half2 a01 = *(__half2*)&acc2h[t][0];
                __half2 a23 = *(__half2*)&acc2h[t][1];
                float v0 = sigmoidf_(__low2float(a01)  + bb.x);
                float v1 = sigmoidf_(__high2float(a01) + bb.y);
                float v2 = sigmoidf_(__low2float(a23)  + bb.x);
                float v3 = sigmoidf_(__high2float(a23) + bb.y);
                s2a = fmaf(v0, v0, s2a); s2a = fmaf(v1, v1, s2a);
                s2b = fmaf(v2, v2, s2b); s2b = fmaf(v3, v3, s2b);
                __half2 t01 = __floats2half2_rn(v0, v1);
                __half2 t23 = __floats2half2_rn(v2, v3);
                uint32_t off = ((uint32_t)(col * 2)) ^ swc;
                *(uint32_t*)(sm8 + (f1 - sb) + off) = *(uint32_t*)&t01;
                *(uint32_t*)(sm8 + (f2 - sb) + off) = *(uint32_t*)&t23;
            }
            s2a += __shfl_xor_sync(FULL, s2a, 1); s2a += __shfl_xor_sync(FULL, s2a, 2);
            s2b += __shfl_xor_sync(FULL, s2b, 1); s2b += __shfl_xor_sync(FULL, s2b, 2);
            if ((lane & 3) == 0) { sS2[gr1] = s2a; sS2[gr2] = s2b; }
            __syncwarp();
        }

        // ---- GEMM3 (fp32 acc): dot' = -2 f.p  (104 mma) ----
        float acc3[26][4];
        #pragma unroll
        for (int t = 0; t < 26; t++) { acc3[t][0]=0.f; acc3[t][1]=0.f; acc3[t][2]=0.f; acc3[t][3]=0.f; }
        {
            uint32_t a3r[4][4];
            #pragma unroll
            for (int kk = 0; kk < 4; kk++) ldm4(a3r[kk], aF + (((kk * 32) | c16) ^ swA));
            #pragma unroll
            for (int kk = 0; kk < 4; kk++) {
                uint32_t kb = ((kk * 32) | cB16) ^ swB;
                #pragma unroll
                for (int np = 0; np < 13; np++) {
                    uint32_t b[4];
                    ldm4(b, bP + np * 2048 + kb);
                    mma16816(acc3[2*np],   a3r[kk], b);
                    mma16816(acc3[2*np+1], a3r[kk], b + 2);
                }
            }
        }

        // ---- epi3: distance + spatial min ----
        {
            const bool A1 = (w * 16 + r1)     < bndw;
            const bool A2 = (w * 16 + r1 + 8) < bndw;
            const float s2r1 = sS2[gr1], s2r2 = sS2[gr2];
            float* wA = sWA + w * NPP;
            float* wB = sWB + w * NPP;
            #pragma unroll
            for (int t = 0; t < 26; t++) {
                int col = t * 8 + e;
                float2 pp = *(float2*)&sP2[col];
                float d0 = fmaxf(acc3[t][0] + s2r1 + pp.x, 0.f);
                float d1 = fmaxf(acc3[t][1] + s2r1 + pp.y, 0.f);
                float d2 = fmaxf(acc3[t][2] + s2r2 + pp.x, 0.f);
                float d3 = fmaxf(acc3[t][3] + s2r2 + pp.y, 0.f);
                float a0 = fminf(A1 ? d0 : INF, A2 ? d2 : INF);
                float a1 = fminf(A1 ? d1 : INF, A2 ? d3 : INF);
                a0 = wmin3(a0); a1 = wmin3(a1);
                if (lane < 4) *(float2*)&wA[col] = make_float2(a0, a1);
                if (hasB) {
                    float b0 = fminf(A1 ? INF : d0, A2 ? INF : d2);
                    float b1v = fminf(A1 ? INF : d1, A2 ? INF : d3);
                    b0 = wmin3(b0); b1v = wmin3(b1v);
                    if (lane < 4) *(float2*)&wB[col] = make_float2(b0, b1v);
                }
            }
        }
        __syncthreads();
        if (tid < NPP) {
            float m = INF;
            #pragma unroll
            for (int ww = 0; ww < 8; ww++) m = fminf(m, sWA[ww * NPP + tid]);
            g_part[(size_t)(tile * 2) * NPP + tid] = m;
            float mb = INF;
            if (hasB) {
                #pragma unroll
                for (int ww = 0; ww < 8; ww++) mb = fminf(mb, sWB[ww * NPP + tid]);
            }
            g_part[(size_t)(tile * 2 + 1) * NPP + tid] = mb;
        }
        __syncthreads();
    }
}

// final: per-image min over tile partials + logits
__global__ void reduce_k(const float* __restrict__ lw, const float* __restrict__ lb,
                         float* __restrict__ logits, float* __restrict__ md)
{
    __shared__ float sm[NPP];
    const int n = blockIdx.x;
    const int tid = threadIdx.x;
    const float INF = __int_as_float(0x7f800000);

    if (tid < NPP) {
        int t0 = (n * HWSZ) >> 7;
        int t1 = (n * HWSZ + HWSZ - 1) >> 7;
        float m = INF;
        for (int t = t0; t <= t1; t++) {
            int nAt = (t * MT) / HWSZ;
            int slot = (nAt == n) ? 0 : 1;
            m = fminf(m, g_part[(size_t)(t * 2 + slot) * NPP + tid]);
        }
        sm[tid] = m;
        if (tid < NP) md[n * NP + tid] = m;
    }
    __syncthreads();

    const int w = tid >> 5, lane = tid & 31;
    for (int cls = w; cls < NCLS; cls += 8) {
        float s = 0.f;
        for (int p = lane; p < NP; p += 32)
            s = fmaf(-sm[p], lw[cls * NP + p], s);
        #pragma unroll
        for (int sh = 16; sh > 0; sh >>= 1)
            s += __shfl_xor_sync(FULL, s, sh);
        if (lane == 0) logits[n * NCLS + cls] = s + lb[cls];
    }
}

extern "C" void kernel_launch(void* const* d_in, const int* in_sizes, int n_in,
                              void* d_out, int out_size)
{
    const float* x    = (const float*)d_in[0];
    const float* W1   = (const float*)d_in[1];
    const float* b1   = (const float*)d_in[2];
    const float* W2   = (const float*)d_in[3];
    const float* b2   = (const float*)d_in[4];
    const float* prot = (const float*)d_in[5];
    const float* lw   = (const float*)d_in[6];
    const float* lb   = (const float*)d_in[7];

    float* out    = (float*)d_out;
    float* logits = out;                       // [256, 10]
    float* md     = out + NIMG * NCLS;         // [256, 200]

    cudaFuncSetAttribute(proto_mma, cudaFuncAttributeMaxDynamicSharedMemorySize, SMEM_TOTAL);
    int sms = 148;
    cudaDeviceGetAttribute(&sms, cudaDevAttrMultiProcessorCount, 0);

    proto_mma<<<sms, TPB, SMEM_TOTAL>>>(x, W1, b1, W2, b2, prot);
    reduce_k<<<NIMG, TPB>>>(lw, lb, logits, md);
}